// round 15
// baseline (speedup 1.0000x reference)
#include <cuda_runtime.h>
#include <cstdint>

// Problem constants (static shapes per reference)
#define B    16
#define S    4096
#define H    1024
#define NS   32           // num sentences
#define NH2  8            // hidden chunks of 128 floats (64 float2 lanes)
#define G    8            // sorted-position groups per batch
#define GS   (S / G)      // positions per group = 512
#define EMB  (B * NS * H)
#define UN   8            // prefetch batch
#define STHR 512          // sort threads
#define RPT  (S / STHR)   // rows per sort thread = 8

// Scratch
__device__ int g_cnt[B * NS];       // counts per (b,s)
__device__ int g_psort[B * S];      // sorted entries: (row<<5)|sid
__device__ int g_done[B];           // per-batch completion tickets

// ---------------------------------------------------------------------------
// Kernel 1: CTAs 0..15 -> per-batch deterministic counting sort (512 thr,
// 8 rows/thread). CTAs 16..191 -> zero `out`; CTA 16 also resets tickets.
// ---------------------------------------------------------------------------
__global__ void __launch_bounds__(STHR) sortzero_kernel(
    const int* __restrict__ m32, float* __restrict__ out)
{
    __shared__ int            sflag;
    __shared__ unsigned short sid_s[S];          // 8 KB
    __shared__ unsigned short m[NS][STHR];       // 32 KB: counts -> offsets
    __shared__ int            cs[NS];
    __shared__ int            base[NS];

    const int tid = threadIdx.x;

    if (blockIdx.x >= B) {
        // zero out[] embeddings (atomic targets must start at 0 every call)
        float4* o4 = (float4*)out;
        const float4 z = make_float4(0.f, 0.f, 0.f, 0.f);
        const int nz  = 176 * STHR;
        for (int i = (blockIdx.x - B) * STHR + tid; i < EMB / 4; i += nz)
            o4[i] = z;
        if (blockIdx.x == B && tid < B) g_done[tid] = 0;
        return;
    }
    const int b = blockIdx.x;

    // mask dtype detect: int64 ids in [0,32) -> odd int32 words all zero
    if (tid == 0) sflag = 0;
    __syncthreads();
    if (tid < 64 && m32[2 * tid + 1] != 0) sflag = 1;   // race-free: all write 1
    __syncthreads();
    const int st = sflag ? 1 : 2;

    for (int i = tid; i < S; i += STHR)
        sid_s[i] = (unsigned short)(m32[((size_t)b * S + i) * st] & (NS - 1));
    for (int k = tid; k < NS * STHR; k += STHR)
        ((unsigned short*)m)[k] = 0;
    __syncthreads();

    {   // per-thread counts over exclusive RPT-row block
        const int r0 = tid * RPT;
        #pragma unroll
        for (int k = 0; k < RPT; k++)
            m[sid_s[r0 + k]][tid]++;
    }
    __syncthreads();

    {   // per-sentence total + exclusive scan over STHR thread columns.
        // 16 warps; each handles 2 sentences; lane l covers 16 columns.
        const int w = tid >> 5, l = tid & 31;
        for (int s = w; s < NS; s += 16) {
            int part = 0;
            #pragma unroll
            for (int k = 0; k < 16; k++) part += m[s][16 * l + k];
            int run = part;
            #pragma unroll
            for (int d = 1; d < 32; d <<= 1) {
                int n = __shfl_up_sync(0xffffffff, run, d);
                if (l >= d) run += n;
            }
            int excl = run - part;
            if (l == 31) cs[s] = run;
            int a = excl;
            #pragma unroll
            for (int k = 0; k < 16; k++) {
                int t0 = m[s][16 * l + k];
                m[s][16 * l + k] = (unsigned short)a;
                a += t0;
            }
        }
    }
    __syncthreads();

    if (tid == 0) {
        int run = 0;
        #pragma unroll
        for (int s = 0; s < NS; s++) { base[s] = run; run += cs[s]; }
    }
    __syncthreads();

    {   // ordered scatter (stable, deterministic)
        const int r0 = tid * RPT;
        int* gp = g_psort + (size_t)b * S;
        #pragma unroll
        for (int k = 0; k < RPT; k++) {
            const int row = r0 + k;
            const int s   = sid_s[row];
            const int p   = base[s] + m[s][tid];
            m[s][tid]++;
            gp[p] = (row << 5) | s;
        }
    }
    if (tid < NS) g_cnt[b * NS + tid] = cs[tid];
}

// ---------------------------------------------------------------------------
// Kernel 2: segment-sum over SORTED rows, register accumulation, float
// atomic flush to `out` at segment boundaries only. Grid: B*NH2*G = 1024
// CTAs, 128 thr, 2 KB smem -> ~7 CTAs/SM, one wave. Last CTA of each batch
// (ticket) scales that batch by 1/count (L2-hot) and writes the tail.
// fp atomic ordering varies at ~1e-7 rel level << 1e-3 tolerance.
// ---------------------------------------------------------------------------
__global__ void __launch_bounds__(128) accum_kernel(const float* __restrict__ x,
                                                    float* __restrict__ out,
                                                    int out_size)
{
    __shared__ int   ps[GS];   // 2 KB
    __shared__ int   s_old;
    __shared__ float sc_inv[NS];

    const int tid = threadIdx.x;
    const int bx  = blockIdx.x;
    const int b   = bx >> 6;             // / (NH2*G)
    const int rem = bx & 63;
    const int hch = rem >> 3;            // hidden chunk (0..7)
    const int g   = rem & 7;             // sorted-position group
    const int hx  = tid & 63;
    const int ly  = tid >> 6;

    const int* gp_in = g_psort + (size_t)b * S + g * GS;
    for (int i = tid; i < GS; i += 128) ps[i] = gp_in[i];
    __syncthreads();

    const float2* xb = (const float2*)(x + (size_t)b * S * H + hch * 128) + hx;
    float* obase = out + (size_t)b * NS * H + hch * 128 + 2 * hx;

    const int p0 = ly * (GS / 2);
    const int pe = p0 + GS / 2;

    float2 rsum = make_float2(0.0f, 0.0f);
    int cur = ps[p0] & 31;

    int    e[UN];
    float2 v[UN];
    #pragma unroll
    for (int u = 0; u < UN; u++) e[u] = ps[p0 + u];
    #pragma unroll
    for (int u = 0; u < UN; u++) v[u] = xb[(size_t)(e[u] >> 5) * (H / 2)];

    for (int pb = p0; pb < pe; pb += UN) {
        const int nb = pb + UN;
        int    ne[UN];
        float2 nv[UN];
        if (nb < pe) {
            #pragma unroll
            for (int u = 0; u < UN; u++) ne[u] = ps[nb + u];
            #pragma unroll
            for (int u = 0; u < UN; u++) nv[u] = xb[(size_t)(ne[u] >> 5) * (H / 2)];
        }
        #pragma unroll
        for (int u = 0; u < UN; u++) {
            const int s = e[u] & 31;
            if (s != cur) {                       // warp-uniform, rare
                float* o = obase + (size_t)cur * H;
                atomicAdd(o,     rsum.x);
                atomicAdd(o + 1, rsum.y);
                cur = s; rsum = v[u];
            } else {
                rsum.x += v[u].x; rsum.y += v[u].y;
            }
        }
        #pragma unroll
        for (int u = 0; u < UN; u++) { e[u] = ne[u]; v[u] = nv[u]; }
    }
    {
        float* o = obase + (size_t)cur * H;
        atomicAdd(o,     rsum.x);
        atomicAdd(o + 1, rsum.y);
    }

    // ---- ticketed per-batch finalize (scale by 1/count) ----
    __threadfence();                       // all threads: drain our atomics
    __syncthreads();
    if (tid == 0) s_old = atomicAdd(&g_done[b], 1);
    __syncthreads();
    if (s_old != NH2 * G - 1) return;      // not the last CTA of this batch

    __threadfence();                       // acquire: see peers' atomics
    if (tid < NS) sc_inv[tid] = 1.0f / (float)g_cnt[b * NS + tid];
    __syncthreads();

    float4* o4 = (float4*)out + (size_t)b * (NS * H / 4);
    for (int k = tid; k < NS * H / 4; k += 128) {
        const int s = k >> 8;              // 256 float4 per sentence
        float4 a = __ldcg(&o4[k]);
        const float inv = sc_inv[s];
        a.x *= inv; a.y *= inv; a.z *= inv; a.w *= inv;
        o4[k] = a;
    }

    if (b == 0 && tid < NS) {              // unique_sents tail, if carried
        const int extra = out_size - EMB;
        if (extra >= 2 * NS)
            ((long long*)out + (EMB / 2))[tid] = (long long)tid;
        else if (extra >= NS)
            out[EMB + tid] = (float)tid;
    }
}

// ---------------------------------------------------------------------------
extern "C" void kernel_launch(void* const* d_in, const int* in_sizes, int n_in,
                              void* d_out, int out_size)
{
    const float* x   = (const float*)d_in[0];
    const int*   m32 = (const int*)d_in[1];
    float*       out = (float*)d_out;

    sortzero_kernel<<<192, STHR>>>(m32, out);
    accum_kernel<<<B * NH2 * G, 128>>>(x, out, out_size);
}

// round 17
// speedup vs baseline: 1.1641x; 1.1641x over previous
#include <cuda_runtime.h>
#include <cstdint>

// Problem constants (static shapes per reference)
#define B    16
#define S    4096
#define H    1024
#define NS   32           // num sentences
#define NH2  8            // hidden chunks of 128 floats (32 float4 lanes)
#define G    8            // sorted-position groups per batch
#define GS   (S / G)      // positions per group = 512
#define EMB  (B * NS * H)
#define UN   4            // prefetch batch (float4 lanes)
#define STHR 512          // sort threads
#define RPT  (S / STHR)   // rows per sort thread = 8

// Scratch
__device__ int g_cnt[B * NS];       // counts per (b,s)
__device__ int g_psort[B * S];      // sorted entries: (row<<5)|sid

// ---------------------------------------------------------------------------
// Kernel 1: CTAs 0..15 -> per-batch deterministic counting sort (512 thr,
// 8 rows/thread). CTAs 16..191 -> zero `out` (atomic targets).
// ---------------------------------------------------------------------------
__global__ void __launch_bounds__(STHR) sortzero_kernel(
    const int* __restrict__ m32, float* __restrict__ out)
{
    __shared__ int            sflag;
    __shared__ unsigned short sid_s[S];          // 8 KB
    __shared__ unsigned short m[NS][STHR];       // 32 KB: counts -> offsets
    __shared__ int            cs[NS];
    __shared__ int            base[NS];

    const int tid = threadIdx.x;

    if (blockIdx.x >= B) {
        float4* o4 = (float4*)out;
        const float4 z = make_float4(0.f, 0.f, 0.f, 0.f);
        const int nz  = 176 * STHR;
        for (int i = (blockIdx.x - B) * STHR + tid; i < EMB / 4; i += nz)
            o4[i] = z;
        return;
    }
    const int b = blockIdx.x;

    // mask dtype detect: int64 ids in [0,32) -> odd int32 words all zero
    if (tid == 0) sflag = 0;
    __syncthreads();
    if (tid < 64 && m32[2 * tid + 1] != 0) sflag = 1;   // race-free: all write 1
    __syncthreads();
    const int st = sflag ? 1 : 2;

    for (int i = tid; i < S; i += STHR)
        sid_s[i] = (unsigned short)(m32[((size_t)b * S + i) * st] & (NS - 1));
    for (int k = tid; k < NS * STHR; k += STHR)
        ((unsigned short*)m)[k] = 0;
    __syncthreads();

    {   // per-thread counts over exclusive RPT-row block
        const int r0 = tid * RPT;
        #pragma unroll
        for (int k = 0; k < RPT; k++)
            m[sid_s[r0 + k]][tid]++;
    }
    __syncthreads();

    {   // per-sentence total + exclusive scan over STHR thread columns.
        // 16 warps; each handles 2 sentences; lane l covers 16 columns.
        const int w = tid >> 5, l = tid & 31;
        for (int s = w; s < NS; s += 16) {
            int part = 0;
            #pragma unroll
            for (int k = 0; k < 16; k++) part += m[s][16 * l + k];
            int run = part;
            #pragma unroll
            for (int d = 1; d < 32; d <<= 1) {
                int n = __shfl_up_sync(0xffffffff, run, d);
                if (l >= d) run += n;
            }
            int excl = run - part;
            if (l == 31) cs[s] = run;
            int a = excl;
            #pragma unroll
            for (int k = 0; k < 16; k++) {
                int t0 = m[s][16 * l + k];
                m[s][16 * l + k] = (unsigned short)a;
                a += t0;
            }
        }
    }
    __syncthreads();

    if (tid == 0) {
        int run = 0;
        #pragma unroll
        for (int s = 0; s < NS; s++) { base[s] = run; run += cs[s]; }
    }
    __syncthreads();

    {   // ordered scatter (stable, deterministic)
        const int r0 = tid * RPT;
        int* gp = g_psort + (size_t)b * S;
        #pragma unroll
        for (int k = 0; k < RPT; k++) {
            const int row = r0 + k;
            const int s   = sid_s[row];
            const int p   = base[s] + m[s][tid];
            m[s][tid]++;
            gp[p] = (row << 5) | s;
        }
    }
    if (tid < NS) g_cnt[b * NS + tid] = cs[tid];
}

// ---------------------------------------------------------------------------
// Kernel 2: segment-sum over SORTED rows, register accumulation (float4
// datapath: 512B per warp per row), atomic flush to `out` only at segment
// boundaries (~3 per thread). Grid: B*NH2*G = 1024 CTAs, 128 thr, 2 KB smem
// -> ~7 CTAs/SM, one wave. hx = tid&31 (float4 lane), ly = tid>>5 (four
// 128-position quarters). Segment-change branches are warp-uniform.
// fp atomic ordering varies at ~1e-7 rel level << 1e-3 tolerance.
// ---------------------------------------------------------------------------
__global__ void __launch_bounds__(128) accum_kernel(const float* __restrict__ x,
                                                    float* __restrict__ out)
{
    __shared__ int ps[GS];   // 2 KB

    const int tid = threadIdx.x;
    const int bx  = blockIdx.x;
    const int b   = bx >> 6;             // / (NH2*G)
    const int rem = bx & 63;
    const int hch = rem >> 3;            // hidden chunk (0..7)
    const int g   = rem & 7;             // sorted-position group
    const int hx  = tid & 31;            // float4 lane within 128-float chunk
    const int ly  = tid >> 5;            // position quarter (0..3)

    const int* gp_in = g_psort + (size_t)b * S + g * GS;
    for (int i = tid; i < GS; i += 128) ps[i] = gp_in[i];
    __syncthreads();

    const float4* xb = (const float4*)(x + (size_t)b * S * H + hch * 128) + hx;
    float* obase = out + (size_t)b * NS * H + hch * 128 + 4 * hx;

    const int p0 = ly * (GS / 4);
    const int pe = p0 + GS / 4;

    float4 rsum = make_float4(0.f, 0.f, 0.f, 0.f);
    int cur = ps[p0] & 31;

    int    e[UN];
    float4 v[UN];
    #pragma unroll
    for (int u = 0; u < UN; u++) e[u] = ps[p0 + u];
    #pragma unroll
    for (int u = 0; u < UN; u++) v[u] = xb[(size_t)(e[u] >> 5) * (H / 4)];

    for (int pb = p0; pb < pe; pb += UN) {
        const int nb = pb + UN;
        int    ne[UN];
        float4 nv[UN];
        if (nb < pe) {
            #pragma unroll
            for (int u = 0; u < UN; u++) ne[u] = ps[nb + u];
            #pragma unroll
            for (int u = 0; u < UN; u++) nv[u] = xb[(size_t)(ne[u] >> 5) * (H / 4)];
        }
        #pragma unroll
        for (int u = 0; u < UN; u++) {
            const int s = e[u] & 31;
            if (s != cur) {                       // warp-uniform, rare
                float* o = obase + (size_t)cur * H;
                atomicAdd(o,     rsum.x);
                atomicAdd(o + 1, rsum.y);
                atomicAdd(o + 2, rsum.z);
                atomicAdd(o + 3, rsum.w);
                cur = s; rsum = v[u];
            } else {
                rsum.x += v[u].x; rsum.y += v[u].y;
                rsum.z += v[u].z; rsum.w += v[u].w;
            }
        }
        #pragma unroll
        for (int u = 0; u < UN; u++) { e[u] = ne[u]; v[u] = nv[u]; }
    }
    {
        float* o = obase + (size_t)cur * H;
        atomicAdd(o,     rsum.x);
        atomicAdd(o + 1, rsum.y);
        atomicAdd(o + 2, rsum.z);
        atomicAdd(o + 3, rsum.w);
    }
}

// ---------------------------------------------------------------------------
// Kernel 3: scale by 1/count (in place) + unique_sents tail.
// One (b,s) per block; float4. 512 CTAs -> parallel, ~3.5us measured (R8).
// ---------------------------------------------------------------------------
__global__ void __launch_bounds__(256) scale_kernel(float* __restrict__ out,
                                                    int out_size)
{
    __shared__ float sinv;
    const int bs  = blockIdx.x;          // b*NS + s
    const int tid = threadIdx.x;

    if (tid == 0) sinv = 1.0f / (float)g_cnt[bs];
    __syncthreads();

    const int idx = bs * 256 + tid;      // float4 index into (B,NS,H)
    float4* o4 = (float4*)out;
    float4 a = o4[idx];
    const float inv = sinv;
    a.x *= inv; a.y *= inv; a.z *= inv; a.w *= inv;
    o4[idx] = a;

    if (bs == 0 && tid < NS) {           // unique_sents tail, if carried
        const int extra = out_size - EMB;
        if (extra >= 2 * NS)
            ((long long*)out + (EMB / 2))[tid] = (long long)tid;
        else if (extra >= NS)
            out[EMB + tid] = (float)tid;
    }
}

// ---------------------------------------------------------------------------
extern "C" void kernel_launch(void* const* d_in, const int* in_sizes, int n_in,
                              void* d_out, int out_size)
{
    const float* x   = (const float*)d_in[0];
    const int*   m32 = (const int*)d_in[1];
    float*       out = (float*)d_out;

    sortzero_kernel<<<192, STHR>>>(m32, out);
    accum_kernel<<<B * NH2 * G, 128>>>(x, out);
    scale_kernel<<<B * NS, 256>>>(out, out_size);
}